// round 4
// baseline (speedup 1.0000x reference)
#include <cuda_runtime.h>

// ATCA/TCA loss, C=10, T=500, N=128, B=256. 4 threads per neuron (125-step
// chunks), exact shuffle merge. Spans: gap values are <0 <= spike values, so
// cluster span max == max spike value -> no gap tracking needed.

#define NEGF (-3.0e30f)

__global__ void atca_zero(float* out) { out[0] = 0.0f; }

#define INS4(x) do { float _x = (x); \
    float _a0 = fmaxf(t40, _x), _b0 = fminf(t40, _x); \
    float _a1 = fmaxf(t41, _b0), _b1 = fminf(t41, _b0); \
    float _a2 = fmaxf(t42, _b1), _b2 = fminf(t42, _b1); \
    t43 = fmaxf(t43, _b2); t42 = _a2; t41 = _a1; t40 = _a0; } while (0)

__global__ void __launch_bounds__(128)
atca4(const float* __restrict__ vmem, const int* __restrict__ labels,
      float* __restrict__ out)
{
    const int gid    = blockIdx.x * 128 + threadIdx.x;
    const int neuron = gid >> 2;          // 0..32767
    const int c      = gid & 3;           // chunk 0..3
    const int b      = neuron >> 7;
    const int n      = neuron & 127;
    const int t0     = c * 125;
    const float* __restrict__ p = vmem + ((size_t)b * 500 + t0) * 128 + n;

    // ---- left halo: last spike in [t0-10, t0), k-relative ----
    int hl = -1000;
    if (c != 0) {
        #pragma unroll
        for (int h = 0; h < 10; ++h) {
            const float v = __ldg(p + (h - 10) * 128);
            if (v >= 0.0f) hl = h - 10;
        }
    }
    int   relB = hl + 20;       // mask threshold: s=kk-10 unmasked iff kk > relB
    int   rel  = -1000;         // local piece threshold: new piece iff kk > rel
    int   ns   = 0;             // local piece count
    int   tfk  = 100000;        // first-spike k (only if < 10)
    int   tlk  = -100000;       // last-spike k (only if >= 115)
    float fm = NEGF, cm = NEGF; // first-piece max, current-piece max
    float mid0 = NEGF;          // largest interior-piece max
    float msum = 0.0f;          // sum of interior-piece maxima
    float m0 = NEGF, vmax = NEGF;

    float A[16], Bb[16];

    #pragma unroll
    for (int j = 0; j < 9; ++j) {
        float*       cur = (j & 1) ? Bb : A;
        const float* prv = (j & 1) ? A : Bb;
        #pragma unroll
        for (int k = 0; k < 16; ++k) {
            const int kk = 16 * j + k;
            if (j < 7) {
                cur[k] = __ldg(p + kk * 128);       // always in-bounds
            } else {
                float v = NEGF;
                if (t0 + kk < 500) v = __ldg(p + kk * 128);
                cur[k] = v;
            }
        }
        #pragma unroll
        for (int k = 0; k < 16; ++k) {
            const int kk  = 16 * j + k;             // compile-time
            const float v = cur[k];
            const bool spk = (v >= 0.0f);
            relB = spk ? kk + 20 : relB;            // spikes incl. right overhang
            if (kk >= 10 && kk < 135) {             // compile-time window
                const float vl = (k >= 10) ? cur[k - 10] : prv[k + 6];
                if (kk > relB) m0 = fmaxf(m0, vl);
            }
            vmax = fmaxf(vmax, v);
            if (kk < 125) {                         // own range (compile-time)
                const bool newp = spk && (kk > rel);
                const bool was0 = (ns == 0);
                const bool was1 = (ns == 1);
                const bool ge2  = (ns >= 2);
                fm = (newp && was1) ? cm : fm;
                const bool pm = newp && ge2;        // retire an interior piece
                msum += pm ? cm : 0.0f;
                mid0  = pm ? fmaxf(mid0, cm) : mid0;
                const float cm1 = fmaxf(cm, v);
                cm = newp ? v : (spk ? cm1 : cm);
                ns += newp ? 1 : 0;
                if (kk < 10)   tfk = (newp && was0) ? kk : tfk;
                if (kk >= 115) tlk = spk ? kk : tlk;
                rel = spk ? kk + 10 : rel;
            }
        }
    }
    const float lm = cm;                            // last-piece max
    if (ns == 1) fm = cm;                           // single piece: fm == lm
    const int tf_abs = t0 + tfk;
    const int tl_abs = t0 + tlk;

    // ---- gather the 4 chunk states (warp shuffles, groups of 4 lanes) ----
    const unsigned FULL = 0xffffffffu;
    const int lane  = threadIdx.x & 31;
    const int gbase = lane & ~3;
    int   g_ns[4], g_tf[4], g_tl[4];
    float g_fm[4], g_lm[4], g_mid[4], g_msum[4], g_m0[4], g_vm[4];
    #pragma unroll
    for (int cc = 0; cc < 4; ++cc) {
        const int src = gbase + cc;
        g_ns[cc]   = __shfl_sync(FULL, ns, src);
        g_tf[cc]   = __shfl_sync(FULL, tf_abs, src);
        g_tl[cc]   = __shfl_sync(FULL, tl_abs, src);
        g_fm[cc]   = __shfl_sync(FULL, fm, src);
        g_lm[cc]   = __shfl_sync(FULL, lm, src);
        g_mid[cc]  = __shfl_sync(FULL, mid0, src);
        g_msum[cc] = __shfl_sync(FULL, msum, src);
        g_m0[cc]   = __shfl_sync(FULL, m0, src);
        g_vm[cc]   = __shfl_sync(FULL, vmax, src);
    }

    float contrib = 0.0f;
    if (c == 0) {
        const float m0g = fmaxf(fmaxf(g_m0[0], g_m0[1]), fmaxf(g_m0[2], g_m0[3]));
        const float vmg = fmaxf(fmaxf(g_vm[0], g_vm[1]), fmaxf(g_vm[2], g_vm[3]));

        int nc = 0; float tot = 0.0f;
        float t40 = NEGF, t41 = NEGF, t42 = NEGF, t43 = NEGF;
        bool ov = false, valid = false;
        float open = NEGF; int last_t = -100000;
        #pragma unroll
        for (int cc = 0; cc < 4; ++cc) {
            if (g_ns[cc] == 0) continue;            // spike-free chunk
            const bool conn = (g_tf[cc] - last_t) <= 10;
            if (conn) {
                open = fmaxf(open, g_fm[cc]);       // first piece extends chain
            } else {
                if (valid) { ++nc; tot += open; INS4(open); }
                open = g_fm[cc]; valid = true;      // first piece starts chain
            }
            if (g_ns[cc] >= 2) {
                ++nc; tot += open; INS4(open);      // chain closes inside chunk
                const int mc = g_ns[cc] - 2;        // interior pieces
                nc += mc; tot += g_msum[cc];
                if (mc >= 1) INS4(g_mid[cc]);
                if (mc >= 2) ov = true;             // top-4 may be inexact
                open = g_lm[cc]; valid = true;      // last piece opens chain
            }
            last_t = g_tl[cc];
        }
        if (valid) { ++nc; tot += open; INS4(open); }

        const int label = labels[neuron];
        if (label > nc) {
            const bool any_un = (m0g > -1.0e29f);
            if (!any_un) {
                contrib = vmg;                      // full0: everything masked
            } else {
                float m_rest;
                if (nc > 0) {
                    m_rest = m0g;   // argmax is a spike -> mask2 == mask
                } else {
                    // cold: no spikes at all — recompute argmax window
                    int tm = 0; float vm = NEGF;
                    for (int t = 0; t < 500; ++t) {
                        const float v = __ldg(p + t * 128);
                        if (v > vm) { vm = v; tm = t; }
                    }
                    float v2 = NEGF;
                    for (int t = 0; t < 500; ++t)
                        if (t < tm - 5 || t > tm + 5)
                            v2 = fmaxf(v2, __ldg(p + t * 128));
                    const bool full2 = (tm <= 5) && (tm + 5 >= 499);
                    m_rest = full2 ? vmg : v2;
                }
                const float dE = (float)(label - nc);
                contrib = -((m0g + (dE - 1.0f) * m_rest) / dE);
            }
        } else if (label < nc) {
            if (ov && label >= 1) {
                // rare exact top-4 recompute (serial rescan)
                t40 = t41 = t42 = t43 = NEGF;
                int last = -1000; float cmx = NEGF; bool open2 = false;
                for (int t = 0; t < 500; ++t) {
                    const float v = __ldg(p + t * 128);
                    if (v >= 0.0f) {
                        if (t - last > 10) {
                            if (open2) INS4(cmx);
                            cmx = v; open2 = true;
                        } else {
                            cmx = fmaxf(cmx, v);
                        }
                        last = t;
                    }
                }
                if (open2) INS4(cmx);
            }
            float s = tot;                          // sum(smallest nc-label)
            if (label >= 1) s -= t40;
            if (label >= 2) s -= t41;
            if (label >= 3) s -= t42;
            if (label >= 4) s -= t43;
            contrib = s / (float)(nc - label);
        }
        out[1 + neuron] = (float)nc;
    }

    // ---- block loss reduction, one atomic per block ----
    float val = contrib;
    #pragma unroll
    for (int off = 16; off > 0; off >>= 1)
        val += __shfl_down_sync(FULL, val, off);
    __shared__ float ws[4];
    if ((threadIdx.x & 31) == 0) ws[threadIdx.x >> 5] = val;
    __syncthreads();
    if (threadIdx.x == 0) atomicAdd(out, ws[0] + ws[1] + ws[2] + ws[3]);
}

extern "C" void kernel_launch(void* const* d_in, const int* in_sizes, int n_in,
                              void* d_out, int out_size) {
    const float* vmem   = (const float*)d_in[0];
    const int*   labels = (const int*)d_in[2];
    float* out = (float*)d_out;

    atca_zero<<<1, 1>>>(out);
    // 32768 neurons * 4 chunk-threads = 131072 threads = 1024 blocks of 128
    atca4<<<1024, 128>>>(vmem, labels, out);
}